// round 7
// baseline (speedup 1.0000x reference)
#include <cuda_runtime.h>

#define NNODES 50000
#define NEDGES 800000
#define FDIM 64
#define NCLS 16
#define CAP 128   // per-node edge capacity (deg ~ Poisson(16); P(deg>128) ~ 0)

// ---- device scratch (allocation-free) ----
__device__ int   g_cnt[NNODES];                  // per-node fill counters
__device__ float g_dinv[NNODES];
__device__ int2  g_edge[(size_t)NNODES * CAP];   // bucketed edges: {src, w/val bits}
__device__ float g_bufA[(size_t)NNODES * FDIM];  // GEMM outputs (gather source)
__device__ float g_bufB[(size_t)NNODES * FDIM];  // aggregated features

// ---------------- prologue ----------------
__global__ void k_prep(int n) {
    int i = blockIdx.x * blockDim.x + threadIdx.x;
    if (i < n) g_cnt[i] = 0;
}

// bucket (src, w) by destination; only counter atomics
__global__ void k_edge(const int* __restrict__ ei,
                       const float* __restrict__ w, int e) {
    int i = blockIdx.x * blockDim.x + threadIdx.x;
    if (i < e) {
        int r = ei[i];
        int c = ei[e + i];
        int pos = atomicAdd(&g_cnt[c], 1);
        if (pos < CAP)
            g_edge[(size_t)c * CAP + pos] = make_int2(r, __float_as_int(w[i]));
    }
}

// weighted degree from buckets (16 lanes/node) -> dinv
__global__ void k_dinv(int n) {
    int gid = blockIdx.x * blockDim.x + threadIdx.x;
    int node = gid >> 4;
    int q    = gid & 15;
    if (node >= n) return;
    int cnt = g_cnt[node];
    if (cnt > CAP) cnt = CAP;
    const size_t base = (size_t)node * CAP;
    float s = 0.0f;
    for (int i = q; i < cnt; i += 16)
        s += __int_as_float(__ldg(&g_edge[base + i].y));
#pragma unroll
    for (int off = 8; off; off >>= 1)
        s += __shfl_xor_sync(0xffffffffu, s, off, 16);
    if (q == 0) g_dinv[node] = rsqrtf(1.0f + s);   // +1 = self-loop weight
}

// rewrite bucket weights: w -> dinv[src]*w  (dinv[dst] factored into agg epilogue)
__global__ void k_bnorm(int n) {
    int gid = blockIdx.x * blockDim.x + threadIdx.x;
    int node = gid >> 4;
    int q    = gid & 15;
    if (node >= n) return;
    int cnt = g_cnt[node];
    if (cnt > CAP) cnt = CAP;
    const size_t base = (size_t)node * CAP;
    for (int i = q; i < cnt; i += 16) {
        int2 ed = g_edge[base + i];
        float val = __ldg(g_dinv + ed.x) * __int_as_float(ed.y);
        g_edge[base + i].y = __float_as_int(val);
    }
}

// ---------------- 64x64 GEMM: bufA = act(X [+bias]) @ W ----------------
// 64 rows/block, 128 threads, thread tile 4 rows x 8 cols.
// Accumulators pack COLUMN pairs -> Ws LDS.128 yields f32x2 operands directly.
template <bool FROM_BUF>
__global__ void __launch_bounds__(128) k_gemm64(const float* __restrict__ Xext,
                         const float* __restrict__ bias,
                         const float* __restrict__ W, int n) {
    __shared__ __align__(16) float Ws[FDIM * FDIM];   // [k][c] row-major
    __shared__ __align__(16) float Xs[FDIM][68];      // [row][k], padded
    const int tid = threadIdx.x;                      // 0..127

    // W: straight float4 copy
    {
        const float4* W4 = (const float4*)W;
        float4* Ws4 = (float4*)Ws;
#pragma unroll
        for (int i = tid; i < FDIM * FDIM / 4; i += 128)
            Ws4[i] = W4[i];
    }

    // X tile: coalesced float4 loads, bias+relu fused, natural layout
    const int row0 = blockIdx.x * 64;
    const float* X = FROM_BUF ? g_bufB : Xext;
    {
        const int kq = tid & 15;
        float4 b4 = make_float4(0.f, 0.f, 0.f, 0.f);
        if (FROM_BUF) b4 = *(const float4*)&bias[kq * 4];
#pragma unroll
        for (int i = tid; i < 64 * 16; i += 128) {
            int rr = i >> 4;
            int row = row0 + rr;
            float4 v = make_float4(0.f, 0.f, 0.f, 0.f);
            if (row < n) v = *(const float4*)&X[(size_t)row * FDIM + kq * 4];
            if (FROM_BUF) {
                v.x = fmaxf(v.x + b4.x, 0.f);
                v.y = fmaxf(v.y + b4.y, 0.f);
                v.z = fmaxf(v.z + b4.z, 0.f);
                v.w = fmaxf(v.w + b4.w, 0.f);
            }
            *(float4*)&Xs[rr][kq * 4] = v;
        }
    }
    __syncthreads();

    const int c0 = (tid & 7) * 8;    // 8 output cols
    const int r0 = (tid >> 3) * 4;   // 4 rows within tile

    // acc[j][p]: f32x2 over cols (c0+2p, c0+2p+1) for row r0+j
    unsigned long long acc[4][4];
#pragma unroll
    for (int j = 0; j < 4; j++)
#pragma unroll
        for (int p = 0; p < 4; p++) acc[j][p] = 0ull;

#pragma unroll
    for (int k = 0; k < FDIM; k++) {
        float a0 = Xs[r0 + 0][k];
        float a1 = Xs[r0 + 1][k];
        float a2 = Xs[r0 + 2][k];
        float a3 = Xs[r0 + 3][k];
        unsigned long long ad0, ad1, ad2, ad3;
        asm("mov.b64 %0, {%1, %1};" : "=l"(ad0) : "f"(a0));
        asm("mov.b64 %0, {%1, %1};" : "=l"(ad1) : "f"(a1));
        asm("mov.b64 %0, {%1, %1};" : "=l"(ad2) : "f"(a2));
        asm("mov.b64 %0, {%1, %1};" : "=l"(ad3) : "f"(a3));
        ulonglong2 b01 = *(const ulonglong2*)&Ws[k * FDIM + c0];      // cols c0..c0+3
        ulonglong2 b23 = *(const ulonglong2*)&Ws[k * FDIM + c0 + 4];  // cols c0+4..c0+7
        asm("fma.rn.f32x2 %0, %1, %2, %0;" : "+l"(acc[0][0]) : "l"(ad0), "l"(b01.x));
        asm("fma.rn.f32x2 %0, %1, %2, %0;" : "+l"(acc[0][1]) : "l"(ad0), "l"(b01.y));
        asm("fma.rn.f32x2 %0, %1, %2, %0;" : "+l"(acc[0][2]) : "l"(ad0), "l"(b23.x));
        asm("fma.rn.f32x2 %0, %1, %2, %0;" : "+l"(acc[0][3]) : "l"(ad0), "l"(b23.y));
        asm("fma.rn.f32x2 %0, %1, %2, %0;" : "+l"(acc[1][0]) : "l"(ad1), "l"(b01.x));
        asm("fma.rn.f32x2 %0, %1, %2, %0;" : "+l"(acc[1][1]) : "l"(ad1), "l"(b01.y));
        asm("fma.rn.f32x2 %0, %1, %2, %0;" : "+l"(acc[1][2]) : "l"(ad1), "l"(b23.x));
        asm("fma.rn.f32x2 %0, %1, %2, %0;" : "+l"(acc[1][3]) : "l"(ad1), "l"(b23.y));
        asm("fma.rn.f32x2 %0, %1, %2, %0;" : "+l"(acc[2][0]) : "l"(ad2), "l"(b01.x));
        asm("fma.rn.f32x2 %0, %1, %2, %0;" : "+l"(acc[2][1]) : "l"(ad2), "l"(b01.y));
        asm("fma.rn.f32x2 %0, %1, %2, %0;" : "+l"(acc[2][2]) : "l"(ad2), "l"(b23.x));
        asm("fma.rn.f32x2 %0, %1, %2, %0;" : "+l"(acc[2][3]) : "l"(ad2), "l"(b23.y));
        asm("fma.rn.f32x2 %0, %1, %2, %0;" : "+l"(acc[3][0]) : "l"(ad3), "l"(b01.x));
        asm("fma.rn.f32x2 %0, %1, %2, %0;" : "+l"(acc[3][1]) : "l"(ad3), "l"(b01.y));
        asm("fma.rn.f32x2 %0, %1, %2, %0;" : "+l"(acc[3][2]) : "l"(ad3), "l"(b23.x));
        asm("fma.rn.f32x2 %0, %1, %2, %0;" : "+l"(acc[3][3]) : "l"(ad3), "l"(b23.y));
    }

    // epilogue: unpack col pairs, 2 float4 stores per row
#pragma unroll
    for (int j = 0; j < 4; j++) {
        int row = row0 + r0 + j;
        if (row < n) {
            float o[8];
#pragma unroll
            for (int p = 0; p < 4; p++)
                asm("mov.b64 {%0, %1}, %2;" : "=f"(o[2 * p]), "=f"(o[2 * p + 1]) : "l"(acc[j][p]));
            float* dst = g_bufA + (size_t)row * FDIM + c0;
            *(float4*)dst       = make_float4(o[0], o[1], o[2], o[3]);
            *(float4*)(dst + 4) = make_float4(o[4], o[5], o[6], o[7]);
        }
    }
}

// ---------------- pull aggregation: bufB[v] = dv*( sum val*bufA[src] + dv*bufA[v] ) ----------------
__global__ void k_agg_pull(int n) {
    int gid = blockIdx.x * blockDim.x + threadIdx.x;
    int node = gid >> 4;
    int q    = gid & 15;
    if (node >= n) return;

    int cnt = g_cnt[node];
    if (cnt > CAP) cnt = CAP;
    float dv = g_dinv[node];
    const size_t base = (size_t)node * CAP;

    float4 a = __ldg(reinterpret_cast<const float4*>(g_bufA + (size_t)node * FDIM) + q);
    float4 acc = make_float4(a.x * dv, a.y * dv, a.z * dv, a.w * dv);

    int i = 0;
    for (; i + 4 <= cnt; i += 4) {
        int2 e0 = __ldg(g_edge + base + i + 0);
        int2 e1 = __ldg(g_edge + base + i + 1);
        int2 e2 = __ldg(g_edge + base + i + 2);
        int2 e3 = __ldg(g_edge + base + i + 3);
        float n0 = __int_as_float(e0.y);
        float n1 = __int_as_float(e1.y);
        float n2 = __int_as_float(e2.y);
        float n3 = __int_as_float(e3.y);
        float4 x0 = __ldg(reinterpret_cast<const float4*>(g_bufA + (size_t)e0.x * FDIM) + q);
        float4 x1 = __ldg(reinterpret_cast<const float4*>(g_bufA + (size_t)e1.x * FDIM) + q);
        float4 x2 = __ldg(reinterpret_cast<const float4*>(g_bufA + (size_t)e2.x * FDIM) + q);
        float4 x3 = __ldg(reinterpret_cast<const float4*>(g_bufA + (size_t)e3.x * FDIM) + q);
        acc.x += n0 * x0.x + n1 * x1.x + n2 * x2.x + n3 * x3.x;
        acc.y += n0 * x0.y + n1 * x1.y + n2 * x2.y + n3 * x3.y;
        acc.z += n0 * x0.z + n1 * x1.z + n2 * x2.z + n3 * x3.z;
        acc.w += n0 * x0.w + n1 * x1.w + n2 * x2.w + n3 * x3.w;
    }
    for (; i < cnt; i++) {
        int2 e0 = __ldg(g_edge + base + i);
        float n0 = __int_as_float(e0.y);
        float4 x0 = __ldg(reinterpret_cast<const float4*>(g_bufA + (size_t)e0.x * FDIM) + q);
        acc.x += n0 * x0.x;
        acc.y += n0 * x0.y;
        acc.z += n0 * x0.z;
        acc.w += n0 * x0.w;
    }
    acc.x *= dv; acc.y *= dv; acc.z *= dv; acc.w *= dv;
    reinterpret_cast<float4*>(g_bufB + (size_t)node * FDIM)[q] = acc;
}

// ---------------- head: relu(bufB + b2) @ Wout + bout -> softmax ----------------
__global__ void k_head(const float* __restrict__ b2,
                       const float* __restrict__ Wout,
                       const float* __restrict__ bout,
                       float* __restrict__ out, int n) {
    __shared__ float Ws[FDIM * NCLS];
    __shared__ float Hs[8][FDIM + 1];
    const int tid = threadIdx.x;   // 0..127

    for (int i = tid; i < FDIM * NCLS; i += 128) Ws[i] = Wout[i];

    int row0 = blockIdx.x * 8;
    for (int i = tid; i < 8 * FDIM; i += 128) {
        int rr = i >> 6, k = i & 63;
        int row = row0 + rr;
        float v = (row < n) ? g_bufB[(size_t)row * FDIM + k] : 0.0f;
        Hs[rr][k] = fmaxf(v + b2[k], 0.0f);
    }
    __syncthreads();

    int rr = tid >> 4;
    int c  = tid & 15;
    int row = row0 + rr;
    if (row < n) {
        float acc = bout[c];
#pragma unroll
        for (int k = 0; k < FDIM; k++)
            acc += Hs[rr][k] * Ws[k * NCLS + c];
        float m = acc;
#pragma unroll
        for (int off = 8; off; off >>= 1)
            m = fmaxf(m, __shfl_xor_sync(0xffffffffu, m, off, 16));
        float ex = __expf(acc - m);
        float s = ex;
#pragma unroll
        for (int off = 8; off; off >>= 1)
            s += __shfl_xor_sync(0xffffffffu, s, off, 16);
        out[(size_t)row * NCLS + c] = ex / s;
    }
}

// ---------------- launch ----------------
extern "C" void kernel_launch(void* const* d_in, const int* in_sizes, int n_in,
                              void* d_out, int out_size) {
    const float* x    = (const float*)d_in[0];
    const int*   ei   = (const int*)d_in[1];    // int32 (JAX x64 disabled)
    const float* w    = (const float*)d_in[2];
    const float* W1   = (const float*)d_in[3];
    const float* b1   = (const float*)d_in[4];
    const float* W2   = (const float*)d_in[5];
    const float* b2   = (const float*)d_in[6];
    const float* Wout = (const float*)d_in[7];
    const float* bout = (const float*)d_in[8];
    float*       out  = (float*)d_out;

    const int n = in_sizes[0] / FDIM;   // 50000
    const int e = in_sizes[2];          // 800000

    const int TB = 256;
    int gemmGrid = (n + 63) / 64;
    int lanGrid  = (int)(((size_t)n * 16 + TB - 1) / TB);

    // prologue: bucket edges, dinv from buckets, prenormalize bucket weights
    k_prep<<<(n + TB - 1) / TB, TB>>>(n);
    k_edge<<<(e + TB - 1) / TB, TB>>>(ei, w, e);
    k_dinv<<<lanGrid, TB>>>(n);
    k_bnorm<<<lanGrid, TB>>>(n);

    // layer 1
    k_gemm64<false><<<gemmGrid, 128>>>(x, b1, W1, n);
    k_agg_pull<<<lanGrid, TB>>>(n);

    // layer 2 (bias b1 + relu fused into GEMM load)
    k_gemm64<true><<<gemmGrid, 128>>>(x, b1, W2, n);
    k_agg_pull<<<lanGrid, TB>>>(n);

    // head
    k_head<<<(n + 7) / 8, 128>>>(b2, Wout, bout, out, n);
}

// round 8
// speedup vs baseline: 1.0213x; 1.0213x over previous
#include <cuda_runtime.h>

#define NNODES 50000
#define NEDGES 800000
#define FDIM 64
#define NCLS 16
#define CAP 128   // per-node edge capacity (deg ~ Poisson(16); P(deg>128) ~ 0)

// ---- device scratch (allocation-free) ----
__device__ int   g_cnt[NNODES];                  // per-node fill counters
__device__ float g_degw[NNODES];                 // weighted degree
__device__ float g_dinv[NNODES];
__device__ int2  g_edge[(size_t)NNODES * CAP];   // bucketed edges: {src, w bits}
__device__ float g_bufA[(size_t)NNODES * FDIM];  // GEMM outputs (gather source)
__device__ float g_bufB[(size_t)NNODES * FDIM];  // aggregated features

// ---------------- prologue ----------------
__global__ void k_prep(int n) {
    int i = blockIdx.x * blockDim.x + threadIdx.x;
    if (i < n) { g_cnt[i] = 0; g_degw[i] = 1.0f; }  // 1.0 = self-loop weight
}

// bucket (src, w) by destination + accumulate weighted degree
__global__ void k_edge(const int* __restrict__ ei,
                       const float* __restrict__ w, int e) {
    int i = blockIdx.x * blockDim.x + threadIdx.x;
    if (i < e) {
        int   r  = ei[i];
        int   c  = ei[e + i];
        float wv = w[i];
        atomicAdd(&g_degw[c], wv);
        int pos = atomicAdd(&g_cnt[c], 1);
        if (pos < CAP)
            g_edge[(size_t)c * CAP + pos] = make_int2(r, __float_as_int(wv));
    }
}

__global__ void k_dinv(int n) {
    int i = blockIdx.x * blockDim.x + threadIdx.x;
    if (i < n) {
        float d = g_degw[i];
        g_dinv[i] = (d > 0.0f) ? rsqrtf(d) : 0.0f;
    }
}

// ---------------- 64x64 GEMM: bufA = act(X [+bias]) @ W ----------------
// 64 rows/block, 128 threads, thread tile 4 rows x 8 cols.
// Accumulators pack COLUMN pairs -> Ws LDS.128 yields f32x2 operands directly.
template <bool FROM_BUF>
__global__ void __launch_bounds__(128) k_gemm64(const float* __restrict__ Xext,
                         const float* __restrict__ bias,
                         const float* __restrict__ W, int n) {
    __shared__ __align__(16) float Ws[FDIM * FDIM];   // [k][c] row-major
    __shared__ __align__(16) float Xs[FDIM][68];      // [row][k], padded
    const int tid = threadIdx.x;                      // 0..127

    // W: straight float4 copy
    {
        const float4* W4 = (const float4*)W;
        float4* Ws4 = (float4*)Ws;
#pragma unroll
        for (int i = tid; i < FDIM * FDIM / 4; i += 128)
            Ws4[i] = W4[i];
    }

    // X tile: coalesced float4 loads, bias+relu fused, natural layout
    const int row0 = blockIdx.x * 64;
    const float* X = FROM_BUF ? g_bufB : Xext;
    {
        const int kq = tid & 15;
        float4 b4 = make_float4(0.f, 0.f, 0.f, 0.f);
        if (FROM_BUF) b4 = *(const float4*)&bias[kq * 4];
#pragma unroll
        for (int i = tid; i < 64 * 16; i += 128) {
            int rr = i >> 4;
            int row = row0 + rr;
            float4 v = make_float4(0.f, 0.f, 0.f, 0.f);
            if (row < n) v = *(const float4*)&X[(size_t)row * FDIM + kq * 4];
            if (FROM_BUF) {
                v.x = fmaxf(v.x + b4.x, 0.f);
                v.y = fmaxf(v.y + b4.y, 0.f);
                v.z = fmaxf(v.z + b4.z, 0.f);
                v.w = fmaxf(v.w + b4.w, 0.f);
            }
            *(float4*)&Xs[rr][kq * 4] = v;
        }
    }
    __syncthreads();

    const int c0 = (tid & 7) * 8;    // 8 output cols
    const int r0 = (tid >> 3) * 4;   // 4 rows within tile

    // acc[j][p]: f32x2 over cols (c0+2p, c0+2p+1) for row r0+j
    unsigned long long acc[4][4];
#pragma unroll
    for (int j = 0; j < 4; j++)
#pragma unroll
        for (int p = 0; p < 4; p++) acc[j][p] = 0ull;

#pragma unroll
    for (int k = 0; k < FDIM; k++) {
        float a0 = Xs[r0 + 0][k];
        float a1 = Xs[r0 + 1][k];
        float a2 = Xs[r0 + 2][k];
        float a3 = Xs[r0 + 3][k];
        unsigned long long ad0, ad1, ad2, ad3;
        asm("mov.b64 %0, {%1, %1};" : "=l"(ad0) : "f"(a0));
        asm("mov.b64 %0, {%1, %1};" : "=l"(ad1) : "f"(a1));
        asm("mov.b64 %0, {%1, %1};" : "=l"(ad2) : "f"(a2));
        asm("mov.b64 %0, {%1, %1};" : "=l"(ad3) : "f"(a3));
        ulonglong2 b01 = *(const ulonglong2*)&Ws[k * FDIM + c0];      // cols c0..c0+3
        ulonglong2 b23 = *(const ulonglong2*)&Ws[k * FDIM + c0 + 4];  // cols c0+4..c0+7
        asm("fma.rn.f32x2 %0, %1, %2, %0;" : "+l"(acc[0][0]) : "l"(ad0), "l"(b01.x));
        asm("fma.rn.f32x2 %0, %1, %2, %0;" : "+l"(acc[0][1]) : "l"(ad0), "l"(b01.y));
        asm("fma.rn.f32x2 %0, %1, %2, %0;" : "+l"(acc[0][2]) : "l"(ad0), "l"(b23.x));
        asm("fma.rn.f32x2 %0, %1, %2, %0;" : "+l"(acc[0][3]) : "l"(ad0), "l"(b23.y));
        asm("fma.rn.f32x2 %0, %1, %2, %0;" : "+l"(acc[1][0]) : "l"(ad1), "l"(b01.x));
        asm("fma.rn.f32x2 %0, %1, %2, %0;" : "+l"(acc[1][1]) : "l"(ad1), "l"(b01.y));
        asm("fma.rn.f32x2 %0, %1, %2, %0;" : "+l"(acc[1][2]) : "l"(ad1), "l"(b23.x));
        asm("fma.rn.f32x2 %0, %1, %2, %0;" : "+l"(acc[1][3]) : "l"(ad1), "l"(b23.y));
        asm("fma.rn.f32x2 %0, %1, %2, %0;" : "+l"(acc[2][0]) : "l"(ad2), "l"(b01.x));
        asm("fma.rn.f32x2 %0, %1, %2, %0;" : "+l"(acc[2][1]) : "l"(ad2), "l"(b01.y));
        asm("fma.rn.f32x2 %0, %1, %2, %0;" : "+l"(acc[2][2]) : "l"(ad2), "l"(b23.x));
        asm("fma.rn.f32x2 %0, %1, %2, %0;" : "+l"(acc[2][3]) : "l"(ad2), "l"(b23.y));
        asm("fma.rn.f32x2 %0, %1, %2, %0;" : "+l"(acc[3][0]) : "l"(ad3), "l"(b01.x));
        asm("fma.rn.f32x2 %0, %1, %2, %0;" : "+l"(acc[3][1]) : "l"(ad3), "l"(b01.y));
        asm("fma.rn.f32x2 %0, %1, %2, %0;" : "+l"(acc[3][2]) : "l"(ad3), "l"(b23.x));
        asm("fma.rn.f32x2 %0, %1, %2, %0;" : "+l"(acc[3][3]) : "l"(ad3), "l"(b23.y));
    }

    // epilogue: unpack col pairs, 2 float4 stores per row
#pragma unroll
    for (int j = 0; j < 4; j++) {
        int row = row0 + r0 + j;
        if (row < n) {
            float o[8];
#pragma unroll
            for (int p = 0; p < 4; p++)
                asm("mov.b64 {%0, %1}, %2;" : "=f"(o[2 * p]), "=f"(o[2 * p + 1]) : "l"(acc[j][p]));
            float* dst = g_bufA + (size_t)row * FDIM + c0;
            *(float4*)dst       = make_float4(o[0], o[1], o[2], o[3]);
            *(float4*)(dst + 4) = make_float4(o[4], o[5], o[6], o[7]);
        }
    }
}

// ---------------- pull aggregation: bufB[v] = dv*( sum dinv[src]*w*bufA[src] + dv*bufA[v] ) ----------------
__global__ void k_agg_pull(int n) {
    int gid = blockIdx.x * blockDim.x + threadIdx.x;
    int node = gid >> 4;
    int q    = gid & 15;
    if (node >= n) return;

    int cnt = g_cnt[node];
    if (cnt > CAP) cnt = CAP;
    float dv = g_dinv[node];
    const size_t base = (size_t)node * CAP;

    float4 a = __ldg(reinterpret_cast<const float4*>(g_bufA + (size_t)node * FDIM) + q);
    float4 acc = make_float4(a.x * dv, a.y * dv, a.z * dv, a.w * dv);

    int i = 0;
    for (; i + 4 <= cnt; i += 4) {
        int2 e0 = __ldg(g_edge + base + i + 0);
        int2 e1 = __ldg(g_edge + base + i + 1);
        int2 e2 = __ldg(g_edge + base + i + 2);
        int2 e3 = __ldg(g_edge + base + i + 3);
        float n0 = __ldg(g_dinv + e0.x) * __int_as_float(e0.y);
        float n1 = __ldg(g_dinv + e1.x) * __int_as_float(e1.y);
        float n2 = __ldg(g_dinv + e2.x) * __int_as_float(e2.y);
        float n3 = __ldg(g_dinv + e3.x) * __int_as_float(e3.y);
        float4 x0 = __ldg(reinterpret_cast<const float4*>(g_bufA + (size_t)e0.x * FDIM) + q);
        float4 x1 = __ldg(reinterpret_cast<const float4*>(g_bufA + (size_t)e1.x * FDIM) + q);
        float4 x2 = __ldg(reinterpret_cast<const float4*>(g_bufA + (size_t)e2.x * FDIM) + q);
        float4 x3 = __ldg(reinterpret_cast<const float4*>(g_bufA + (size_t)e3.x * FDIM) + q);
        acc.x += n0 * x0.x + n1 * x1.x + n2 * x2.x + n3 * x3.x;
        acc.y += n0 * x0.y + n1 * x1.y + n2 * x2.y + n3 * x3.y;
        acc.z += n0 * x0.z + n1 * x1.z + n2 * x2.z + n3 * x3.z;
        acc.w += n0 * x0.w + n1 * x1.w + n2 * x2.w + n3 * x3.w;
    }
    for (; i < cnt; i++) {
        int2 e0 = __ldg(g_edge + base + i);
        float n0 = __ldg(g_dinv + e0.x) * __int_as_float(e0.y);
        float4 x0 = __ldg(reinterpret_cast<const float4*>(g_bufA + (size_t)e0.x * FDIM) + q);
        acc.x += n0 * x0.x;
        acc.y += n0 * x0.y;
        acc.z += n0 * x0.z;
        acc.w += n0 * x0.w;
    }
    acc.x *= dv; acc.y *= dv; acc.z *= dv; acc.w *= dv;
    reinterpret_cast<float4*>(g_bufB + (size_t)node * FDIM)[q] = acc;
}

// ---------------- head: relu(bufB + b2) @ Wout + bout -> softmax ----------------
__global__ void k_head(const float* __restrict__ b2,
                       const float* __restrict__ Wout,
                       const float* __restrict__ bout,
                       float* __restrict__ out, int n) {
    __shared__ float Ws[FDIM * NCLS];
    __shared__ float Hs[8][FDIM + 1];
    const int tid = threadIdx.x;   // 0..127

    for (int i = tid; i < FDIM * NCLS; i += 128) Ws[i] = Wout[i];

    int row0 = blockIdx.x * 8;
    for (int i = tid; i < 8 * FDIM; i += 128) {
        int rr = i >> 6, k = i & 63;
        int row = row0 + rr;
        float v = (row < n) ? g_bufB[(size_t)row * FDIM + k] : 0.0f;
        Hs[rr][k] = fmaxf(v + b2[k], 0.0f);
    }
    __syncthreads();

    int rr = tid >> 4;
    int c  = tid & 15;
    int row = row0 + rr;
    if (row < n) {
        float acc = bout[c];
#pragma unroll
        for (int k = 0; k < FDIM; k++)
            acc += Hs[rr][k] * Ws[k * NCLS + c];
        float m = acc;
#pragma unroll
        for (int off = 8; off; off >>= 1)
            m = fmaxf(m, __shfl_xor_sync(0xffffffffu, m, off, 16));
        float ex = __expf(acc - m);
        float s = ex;
#pragma unroll
        for (int off = 8; off; off >>= 1)
            s += __shfl_xor_sync(0xffffffffu, s, off, 16);
        out[(size_t)row * NCLS + c] = ex / s;
    }
}

// ---------------- launch ----------------
extern "C" void kernel_launch(void* const* d_in, const int* in_sizes, int n_in,
                              void* d_out, int out_size) {
    const float* x    = (const float*)d_in[0];
    const int*   ei   = (const int*)d_in[1];    // int32 (JAX x64 disabled)
    const float* w    = (const float*)d_in[2];
    const float* W1   = (const float*)d_in[3];
    const float* b1   = (const float*)d_in[4];
    const float* W2   = (const float*)d_in[5];
    const float* b2   = (const float*)d_in[6];
    const float* Wout = (const float*)d_in[7];
    const float* bout = (const float*)d_in[8];
    float*       out  = (float*)d_out;

    const int n = in_sizes[0] / FDIM;   // 50000
    const int e = in_sizes[2];          // 800000

    const int TB = 256;
    int gemmGrid = (n + 63) / 64;
    int lanGrid  = (int)(((size_t)n * 16 + TB - 1) / TB);

    // prologue: bucket edges + weighted degree (float atomics are cheap), dinv
    k_prep<<<(n + TB - 1) / TB, TB>>>(n);
    k_edge<<<(e + TB - 1) / TB, TB>>>(ei, w, e);
    k_dinv<<<(n + TB - 1) / TB, TB>>>(n);

    // layer 1
    k_gemm64<false><<<gemmGrid, 128>>>(x, b1, W1, n);
    k_agg_pull<<<lanGrid, TB>>>(n);

    // layer 2 (bias b1 + relu fused into GEMM load)
    k_gemm64<true><<<gemmGrid, 128>>>(x, b1, W2, n);
    k_agg_pull<<<lanGrid, TB>>>(n);

    // head
    k_head<<<(n + 7) / 8, 128>>>(b2, Wout, bout, out, n);
}

// round 10
// speedup vs baseline: 1.0464x; 1.0246x over previous
#include <cuda_runtime.h>

#define NNODES 50000
#define NEDGES 800000
#define FDIM 64
#define NCLS 16
#define CAP 128   // per-node edge capacity (deg ~ Binomial(800k,1/50k); max ~40)

typedef unsigned long long ull;

// ---- device scratch (allocation-free) ----
__device__ int   g_cnt[NNODES];                  // per-node fill counters
__device__ float g_degw[NNODES];                 // weighted degree
__device__ float g_dinv[NNODES];
__device__ int2  g_edge[(size_t)NNODES * CAP];   // bucketed edges: {src, w bits}
__device__ float g_bufA[(size_t)NNODES * FDIM];  // layer-1 output
__device__ float g_bufB[(size_t)NNODES * FDIM];  // layer-2 output

// ---------------- prologue ----------------
__global__ void k_prep(int n) {
    int i = blockIdx.x * blockDim.x + threadIdx.x;
    if (i < n) { g_cnt[i] = 0; g_degw[i] = 1.0f; }  // 1.0 = self-loop weight
}

__global__ void k_edge(const int* __restrict__ ei,
                       const float* __restrict__ w, int e) {
    int i = blockIdx.x * blockDim.x + threadIdx.x;
    if (i < e) {
        int   r  = ei[i];
        int   c  = ei[e + i];
        float wv = w[i];
        atomicAdd(&g_degw[c], wv);
        int pos = atomicAdd(&g_cnt[c], 1);
        if (pos < CAP)
            g_edge[(size_t)c * CAP + pos] = make_int2(r, __float_as_int(wv));
    }
}

__global__ void k_dinv(int n) {
    int i = blockIdx.x * blockDim.x + threadIdx.x;
    if (i < n) {
        float d = g_degw[i];
        g_dinv[i] = (d > 0.0f) ? rsqrtf(d) : 0.0f;
    }
}

// ---------------- fused layer: Y = relu( (Â·Xsrc) @ W + bias ) ----------------
// L==1: Xsrc = Xext (kernel param), Y = g_bufA
// L==2: Xsrc = g_bufA,              Y = g_bufB
// (device-global buffers bound IN DEVICE CODE — never passed from host)
//
// Block = 64 nodes, 256 threads.
// Phase 1: pull-aggregate Z = Â·Xsrc into smem, transposed with XOR swizzle
//          ZT[k][row ^ (k & 60)] (2-way STS conflicts; read at column
//          r0^(k&60) returns rows r0..r0+3 contiguously).
// Phase 2: row-packed 4x4 register-tile GEMM from smem (fma.rn.f32x2),
//          bias + relu fused into the epilogue.
template <int L>
__global__ void __launch_bounds__(256) k_layer(const float* __restrict__ Xext,
                                               const float* __restrict__ bias,
                                               const float* __restrict__ W, int n) {
    __shared__ __align__(16) float Ws[FDIM * FDIM];   // [k][c]
    __shared__ __align__(16) float ZT[FDIM][68];      // [k][node^], padded
    const int tid = threadIdx.x;

    const float* Xsrc = (L == 1) ? Xext : g_bufA;
    float*       Y    = (L == 1) ? g_bufA : g_bufB;

    // load W (float4 copy)
    {
        const float4* W4 = (const float4*)W;
        float4* Ws4 = (float4*)Ws;
#pragma unroll
        for (int i = tid; i < FDIM * FDIM / 4; i += 256)
            Ws4[i] = W4[i];
    }

    const int row0 = blockIdx.x * 64;
    const int q    = tid & 15;      // float4 index within a 64-feature row
    const int grp  = tid >> 4;      // 16 node-groups
    const int colx = 4 * q;         // swizzle constant: (4q+j) & 60 == 4q

    // ---- Phase 1: aggregation (each group handles 4 nodes) ----
#pragma unroll
    for (int s = 0; s < 4; s++) {
        int rr   = grp + 16 * s;    // local node 0..63
        int node = row0 + rr;
        float4 acc = make_float4(0.f, 0.f, 0.f, 0.f);
        if (node < n) {
            int cnt = g_cnt[node];
            if (cnt > CAP) cnt = CAP;
            float dv = g_dinv[node];
            const size_t base = (size_t)node * CAP;

            float4 a = __ldg(reinterpret_cast<const float4*>(Xsrc + (size_t)node * FDIM) + q);
            acc = make_float4(a.x * dv, a.y * dv, a.z * dv, a.w * dv);

            int i = 0;
            for (; i + 4 <= cnt; i += 4) {
                int2 e0 = __ldg(g_edge + base + i + 0);
                int2 e1 = __ldg(g_edge + base + i + 1);
                int2 e2 = __ldg(g_edge + base + i + 2);
                int2 e3 = __ldg(g_edge + base + i + 3);
                float n0 = __ldg(g_dinv + e0.x) * __int_as_float(e0.y);
                float n1 = __ldg(g_dinv + e1.x) * __int_as_float(e1.y);
                float n2 = __ldg(g_dinv + e2.x) * __int_as_float(e2.y);
                float n3 = __ldg(g_dinv + e3.x) * __int_as_float(e3.y);
                float4 x0 = __ldg(reinterpret_cast<const float4*>(Xsrc + (size_t)e0.x * FDIM) + q);
                float4 x1 = __ldg(reinterpret_cast<const float4*>(Xsrc + (size_t)e1.x * FDIM) + q);
                float4 x2 = __ldg(reinterpret_cast<const float4*>(Xsrc + (size_t)e2.x * FDIM) + q);
                float4 x3 = __ldg(reinterpret_cast<const float4*>(Xsrc + (size_t)e3.x * FDIM) + q);
                acc.x += n0 * x0.x + n1 * x1.x + n2 * x2.x + n3 * x3.x;
                acc.y += n0 * x0.y + n1 * x1.y + n2 * x2.y + n3 * x3.y;
                acc.z += n0 * x0.z + n1 * x1.z + n2 * x2.z + n3 * x3.z;
                acc.w += n0 * x0.w + n1 * x1.w + n2 * x2.w + n3 * x3.w;
            }
            for (; i < cnt; i++) {
                int2 e0 = __ldg(g_edge + base + i);
                float n0 = __ldg(g_dinv + e0.x) * __int_as_float(e0.y);
                float4 x0 = __ldg(reinterpret_cast<const float4*>(Xsrc + (size_t)e0.x * FDIM) + q);
                acc.x += n0 * x0.x;
                acc.y += n0 * x0.y;
                acc.z += n0 * x0.z;
                acc.w += n0 * x0.w;
            }
            acc.x *= dv; acc.y *= dv; acc.z *= dv; acc.w *= dv;
        }
        int rsw = rr ^ colx;        // swizzled column
        ZT[4 * q + 0][rsw] = acc.x;
        ZT[4 * q + 1][rsw] = acc.y;
        ZT[4 * q + 2][rsw] = acc.z;
        ZT[4 * q + 3][rsw] = acc.w;
    }
    __syncthreads();

    // ---- Phase 2: GEMM from smem, 4 rows x 4 cols per thread ----
    const int c0 = (tid & 15) * 4;
    const int r0 = (tid >> 4) * 4;

    ull acc01[4] = {0ull, 0ull, 0ull, 0ull};   // rows (r0, r0+1), cols c0..c0+3
    ull acc23[4] = {0ull, 0ull, 0ull, 0ull};   // rows (r0+2, r0+3)

#pragma unroll
    for (int k = 0; k < FDIM; k++) {
        int rsw = r0 ^ (k & 60);
        ulonglong2 av = *(const ulonglong2*)&ZT[k][rsw];   // this thread's row pairs
        float4 bv = *(const float4*)&Ws[k * FDIM + c0];
        ull bd0, bd1, bd2, bd3;
        asm("mov.b64 %0, {%1, %1};" : "=l"(bd0) : "f"(bv.x));
        asm("mov.b64 %0, {%1, %1};" : "=l"(bd1) : "f"(bv.y));
        asm("mov.b64 %0, {%1, %1};" : "=l"(bd2) : "f"(bv.z));
        asm("mov.b64 %0, {%1, %1};" : "=l"(bd3) : "f"(bv.w));
        asm("fma.rn.f32x2 %0, %1, %2, %0;" : "+l"(acc01[0]) : "l"(av.x), "l"(bd0));
        asm("fma.rn.f32x2 %0, %1, %2, %0;" : "+l"(acc01[1]) : "l"(av.x), "l"(bd1));
        asm("fma.rn.f32x2 %0, %1, %2, %0;" : "+l"(acc01[2]) : "l"(av.x), "l"(bd2));
        asm("fma.rn.f32x2 %0, %1, %2, %0;" : "+l"(acc01[3]) : "l"(av.x), "l"(bd3));
        asm("fma.rn.f32x2 %0, %1, %2, %0;" : "+l"(acc23[0]) : "l"(av.y), "l"(bd0));
        asm("fma.rn.f32x2 %0, %1, %2, %0;" : "+l"(acc23[1]) : "l"(av.y), "l"(bd1));
        asm("fma.rn.f32x2 %0, %1, %2, %0;" : "+l"(acc23[2]) : "l"(av.y), "l"(bd2));
        asm("fma.rn.f32x2 %0, %1, %2, %0;" : "+l"(acc23[3]) : "l"(av.y), "l"(bd3));
    }

    // epilogue: unpack row pairs, add bias, relu, store float4 per row
    float4 b4 = *(const float4*)&bias[c0];
    float r0v[4], r1v[4], r2v[4], r3v[4];
#pragma unroll
    for (int c = 0; c < 4; c++) {
        asm("mov.b64 {%0, %1}, %2;" : "=f"(r0v[c]), "=f"(r1v[c]) : "l"(acc01[c]));
        asm("mov.b64 {%0, %1}, %2;" : "=f"(r2v[c]), "=f"(r3v[c]) : "l"(acc23[c]));
    }
    float4 o0 = make_float4(fmaxf(r0v[0] + b4.x, 0.f), fmaxf(r0v[1] + b4.y, 0.f),
                            fmaxf(r0v[2] + b4.z, 0.f), fmaxf(r0v[3] + b4.w, 0.f));
    float4 o1 = make_float4(fmaxf(r1v[0] + b4.x, 0.f), fmaxf(r1v[1] + b4.y, 0.f),
                            fmaxf(r1v[2] + b4.z, 0.f), fmaxf(r1v[3] + b4.w, 0.f));
    float4 o2 = make_float4(fmaxf(r2v[0] + b4.x, 0.f), fmaxf(r2v[1] + b4.y, 0.f),
                            fmaxf(r2v[2] + b4.z, 0.f), fmaxf(r2v[3] + b4.w, 0.f));
    float4 o3 = make_float4(fmaxf(r3v[0] + b4.x, 0.f), fmaxf(r3v[1] + b4.y, 0.f),
                            fmaxf(r3v[2] + b4.z, 0.f), fmaxf(r3v[3] + b4.w, 0.f));
    int row = row0 + r0;
    if (row + 0 < n) *(float4*)&Y[(size_t)(row + 0) * FDIM + c0] = o0;
    if (row + 1 < n) *(float4*)&Y[(size_t)(row + 1) * FDIM + c0] = o1;
    if (row + 2 < n) *(float4*)&Y[(size_t)(row + 2) * FDIM + c0] = o2;
    if (row + 3 < n) *(float4*)&Y[(size_t)(row + 3) * FDIM + c0] = o3;
}

// ---------------- head: bufB @ Wout + bout -> softmax ----------------
// (bias b2 + relu already applied by layer 2's epilogue)
__global__ void k_head(const float* __restrict__ Wout,
                       const float* __restrict__ bout,
                       float* __restrict__ out, int n) {
    __shared__ float Ws[FDIM * NCLS];
    __shared__ float Hs[8][FDIM + 1];
    const int tid = threadIdx.x;   // 0..127

    for (int i = tid; i < FDIM * NCLS; i += 128) Ws[i] = Wout[i];

    int row0 = blockIdx.x * 8;
    for (int i = tid; i < 8 * FDIM; i += 128) {
        int rr = i >> 6, k = i & 63;
        int row = row0 + rr;
        Hs[rr][k] = (row < n) ? g_bufB[(size_t)row * FDIM + k] : 0.0f;
    }
    __syncthreads();

    int rr = tid >> 4;
    int c  = tid & 15;
    int row = row0 + rr;
    if (row < n) {
        float acc = bout[c];
#pragma unroll
        for (int k = 0; k < FDIM; k++)
            acc += Hs[rr][k] * Ws[k * NCLS + c];
        float m = acc;
#pragma unroll
        for (int off = 8; off; off >>= 1)
            m = fmaxf(m, __shfl_xor_sync(0xffffffffu, m, off, 16));
        float ex = __expf(acc - m);
        float s = ex;
#pragma unroll
        for (int off = 8; off; off >>= 1)
            s += __shfl_xor_sync(0xffffffffu, s, off, 16);
        out[(size_t)row * NCLS + c] = ex / s;
    }
}

// ---------------- launch ----------------
extern "C" void kernel_launch(void* const* d_in, const int* in_sizes, int n_in,
                              void* d_out, int out_size) {
    const float* x    = (const float*)d_in[0];
    const int*   ei   = (const int*)d_in[1];    // int32 (JAX x64 disabled)
    const float* w    = (const float*)d_in[2];
    const float* W1   = (const float*)d_in[3];
    const float* b1   = (const float*)d_in[4];
    const float* W2   = (const float*)d_in[5];
    const float* b2   = (const float*)d_in[6];
    const float* Wout = (const float*)d_in[7];
    const float* bout = (const float*)d_in[8];
    float*       out  = (float*)d_out;

    const int n = in_sizes[0] / FDIM;   // 50000
    const int e = in_sizes[2];          // 800000

    const int TB = 256;
    int layerGrid = (n + 63) / 64;

    // prologue: bucket edges + weighted degree, dinv
    k_prep<<<(n + TB - 1) / TB, TB>>>(n);
    k_edge<<<(e + TB - 1) / TB, TB>>>(ei, w, e);
    k_dinv<<<(n + TB - 1) / TB, TB>>>(n);

    // layer 1: g_bufA = relu((Â·x)·W1 + b1)     (buffers bound in device code)
    k_layer<1><<<layerGrid, 256>>>(x, b1, W1, n);
    // layer 2: g_bufB = relu((Â·g_bufA)·W2 + b2)
    k_layer<2><<<layerGrid, 256>>>(x, b2, W2, n);

    // head: softmax(g_bufB·Wout + bout)
    k_head<<<(n + 7) / 8, 128>>>(Wout, bout, out, n);
}